// round 2
// baseline (speedup 1.0000x reference)
#include <cuda_runtime.h>

typedef unsigned long long ull;

// ---------------- device scratch (no allocations allowed) ----------------
__device__ float g_A[256];          // W_ih[:, :64] @ W_num
__device__ float g_C[256];          // W_ih[:, :64] @ b_num + b_ih + b_hh
__device__ float g_FC[256 * 64];    // per-block partial sum of sigmoid(f)*c
__device__ float g_HS[256 * 64];    // per-block partial sum of h_hat

// ---------------- helpers ----------------
__device__ __forceinline__ ull fma2(ull a, ull b, ull c) {
    ull d;
    asm("fma.rn.f32x2 %0, %1, %2, %3;" : "=l"(d) : "l"(a), "l"(b), "l"(c));
    return d;
}
__device__ __forceinline__ float hadd2(ull v) {
    float lo, hi;
    asm("mov.b64 {%0, %1}, %2;" : "=f"(lo), "=f"(hi) : "l"(v));
    return lo + hi;
}
__device__ __forceinline__ float sigm(float x) {
    // 1/(1+e^-x); safe at extremes (exp->inf => 0, exp->0 => 1)
    return __fdividef(1.0f, 1.0f + __expf(-x));
}
__device__ __forceinline__ float tanh_f(float x) {
    // 2/(1+e^-2x) - 1; safe at extremes
    return __fdividef(2.0f, 1.0f + __expf(-2.0f * x)) - 1.0f;
}

// ---------------- kernel 0: fold input projection ----------------
__global__ void precompute_kernel(const float* __restrict__ W_ih,
                                  const float* __restrict__ W_num,
                                  const float* __restrict__ b_num,
                                  const float* __restrict__ b_ih,
                                  const float* __restrict__ b_hh) {
    int g = threadIdx.x;  // 0..255
    float a = 0.f, c = 0.f;
#pragma unroll 8
    for (int d = 0; d < 64; ++d) {
        float w = W_ih[g * 128 + d];  // W_ih is (256,128); use first 64 cols
        a = fmaf(w, W_num[d], a);
        c = fmaf(w, b_num[d], c);
    }
    g_A[g] = a;
    g_C[g] = c + b_ih[g] + b_hh[g];
}

// ---------------- kernel 1: batched LSTM scan + fused epilogue ----------------
// grid = 256 blocks (32 rows each), block = 256 threads (8 warps).
// warp w owns hidden dims [8w, 8w+8) for all 32 rows; lane = row.
// SMEM (floats): sW 16384 | sX 4224 | sH 2176 | sA 256 | sC 256  = 93184 B
#define SMEM_FLOATS 23296
#define SMEM_BYTES  (SMEM_FLOATS * 4)

__global__ __launch_bounds__(256, 2)
void lstm_kernel(const float* __restrict__ x,
                 const float* __restrict__ W_hh,
                 const float* __restrict__ W_aout,
                 const float* __restrict__ b_aout,
                 const float* __restrict__ W_fh,
                 const float* __restrict__ b_fh) {
    extern __shared__ float smem[];
    float* sW = smem;            // [256][64] W_hh rows
    float* sX = smem + 16384;    // [128][33] x tile, transposed + padded
    float* sH = smem + 20608;    // [32][68]  h, padded stride
    float* sA = smem + 22784;    // A (then b_aout|b_fh in epilogue)
    float* sC = smem + 23040;    // C

    const int tid  = threadIdx.x;
    const int lane = tid & 31;          // row within block
    const int wid  = tid >> 5;          // dim chunk
    const int d0   = wid * 8;
    const int r0   = blockIdx.x * 32;

    // stage weights / x tile / zero h
    for (int i = tid; i < 16384; i += 256) sW[i] = W_hh[i];
    for (int i = tid; i < 4096; i += 256) {
        int rr = i >> 7, tt = i & 127;
        sX[tt * 33 + rr] = x[(size_t)(r0 + rr) * 128 + tt];
    }
    for (int i = tid; i < 2176; i += 256) sH[i] = 0.f;
    sA[tid] = g_A[tid];
    sC[tid] = g_C[tid];
    __syncthreads();

    float c[8], hn[8];
#pragma unroll
    for (int u = 0; u < 8; ++u) c[u] = 0.f;

    for (int t = 0; t < 128; ++t) {
        float xv = sX[t * 33 + lane];
        // load full h row (packed pairs) into registers
        ull hp[32];
        const ulonglong2* hv = reinterpret_cast<const ulonglong2*>(sH + lane * 68);
#pragma unroll
        for (int i = 0; i < 16; ++i) {
            ulonglong2 v = hv[i];
            hp[2 * i] = v.x; hp[2 * i + 1] = v.y;
        }
        __syncthreads();  // all loads done before anyone rewrites sH

#pragma unroll
        for (int u = 0; u < 8; ++u) {
            const int d = d0 + u;
            const ulonglong2* Wi = reinterpret_cast<const ulonglong2*>(sW + d * 64);
            const ulonglong2* Wf = reinterpret_cast<const ulonglong2*>(sW + (64 + d) * 64);
            const ulonglong2* Wg = reinterpret_cast<const ulonglong2*>(sW + (128 + d) * 64);
            const ulonglong2* Wo = reinterpret_cast<const ulonglong2*>(sW + (192 + d) * 64);
            ull ai = 0ull, af = 0ull, ag = 0ull, ao = 0ull;
#pragma unroll
            for (int q = 0; q < 16; ++q) {
                ulonglong2 wi = Wi[q], wf = Wf[q], wg = Wg[q], wo = Wo[q];
                ai = fma2(wi.x, hp[2 * q], ai); ai = fma2(wi.y, hp[2 * q + 1], ai);
                af = fma2(wf.x, hp[2 * q], af); af = fma2(wf.y, hp[2 * q + 1], af);
                ag = fma2(wg.x, hp[2 * q], ag); ag = fma2(wg.y, hp[2 * q + 1], ag);
                ao = fma2(wo.x, hp[2 * q], ao); ao = fma2(wo.y, hp[2 * q + 1], ao);
            }
            float gi = hadd2(ai) + fmaf(xv, sA[d],       sC[d]);
            float gf = hadd2(af) + fmaf(xv, sA[64 + d],  sC[64 + d]);
            float gg = hadd2(ag) + fmaf(xv, sA[128 + d], sC[128 + d]);
            float go = hadd2(ao) + fmaf(xv, sA[192 + d], sC[192 + d]);
            float I = sigm(gi), F = sigm(gf), G = tanh_f(gg), O = sigm(go);
            c[u]  = fmaf(F, c[u], I * G);
            hn[u] = O * tanh_f(c[u]);
        }
        // publish new h
        float4* dst = reinterpret_cast<float4*>(sH + lane * 68 + d0);
        dst[0] = make_float4(hn[0], hn[1], hn[2], hn[3]);
        dst[1] = make_float4(hn[4], hn[5], hn[6], hn[7]);
        __syncthreads();  // writes visible before next iteration's loads
    }

    // ---- epilogue: h_hat = h@W_aout.T + b_aout ; f = h_hat@W_fh.T + b_fh ----
    for (int i = tid; i < 4096; i += 256) {
        sW[i]        = W_aout[i];
        sW[4096 + i] = W_fh[i];
    }
    if (tid < 64) { sA[tid] = b_aout[tid]; sA[64 + tid] = b_fh[tid]; }
    __syncthreads();

    // final h
    ull hp[32];
    {
        const ulonglong2* hv = reinterpret_cast<const ulonglong2*>(sH + lane * 68);
#pragma unroll
        for (int i = 0; i < 16; ++i) { ulonglong2 v = hv[i]; hp[2 * i] = v.x; hp[2 * i + 1] = v.y; }
    }
    float hh[8];
#pragma unroll
    for (int u = 0; u < 8; ++u) {
        const int d = d0 + u;
        const ulonglong2* Wa = reinterpret_cast<const ulonglong2*>(sW + d * 64);
        ull acc = 0ull;
#pragma unroll
        for (int q = 0; q < 16; ++q) {
            ulonglong2 w = Wa[q];
            acc = fma2(w.x, hp[2 * q], acc);
            acc = fma2(w.y, hp[2 * q + 1], acc);
        }
        hh[u] = hadd2(acc) + sA[d];
    }
    __syncthreads();
    // publish h_hat rows into sX area (stride 68)
    {
        float4* hdst = reinterpret_cast<float4*>(sX + lane * 68 + d0);
        hdst[0] = make_float4(hh[0], hh[1], hh[2], hh[3]);
        hdst[1] = make_float4(hh[4], hh[5], hh[6], hh[7]);
    }
    __syncthreads();
    ull qp[32];
    {
        const ulonglong2* qv = reinterpret_cast<const ulonglong2*>(sX + lane * 68);
#pragma unroll
        for (int i = 0; i < 16; ++i) { ulonglong2 v = qv[i]; qp[2 * i] = v.x; qp[2 * i + 1] = v.y; }
    }
#pragma unroll
    for (int u = 0; u < 8; ++u) {
        const int d = d0 + u;
        const ulonglong2* Wf2 = reinterpret_cast<const ulonglong2*>(sW + 4096 + d * 64);
        ull acc = 0ull;
#pragma unroll
        for (int q = 0; q < 16; ++q) {
            ulonglong2 w = Wf2[q];
            acc = fma2(w.x, qp[2 * q], acc);
            acc = fma2(w.y, qp[2 * q + 1], acc);
        }
        float fv = hadd2(acc) + sA[64 + d];
        float fc = sigm(fv) * c[u];
        float hs = hh[u];
        // reduce over the 32 rows in this warp
#pragma unroll
        for (int off = 16; off; off >>= 1) {
            fc += __shfl_down_sync(0xffffffffu, fc, off);
            hs += __shfl_down_sync(0xffffffffu, hs, off);
        }
        if (lane == 0) {
            g_FC[blockIdx.x * 64 + d] = fc;
            g_HS[blockIdx.x * 64 + d] = hs;
        }
    }
}

// ---------------- kernel 2: deterministic final reduction + objective cell ----------------
__global__ void final_kernel(float* __restrict__ out,
                             const float* __restrict__ W_iouh,
                             const float* __restrict__ b_iouh,
                             const float* __restrict__ W_oout,
                             const float* __restrict__ b_oout) {
    __shared__ float s_fc[64], s_hs[64], s_iou[192], s_hobj[64];
    int tid = threadIdx.x;
    if (tid < 64) {
        float fc = 0.f, hs = 0.f;
#pragma unroll 8
        for (int b = 0; b < 256; ++b) {
            fc += g_FC[b * 64 + tid];
            hs += g_HS[b * 64 + tid];
        }
        s_fc[tid] = fc;
        s_hs[tid] = hs;
    }
    __syncthreads();
    if (tid < 192) {
        float acc = b_iouh[tid];
#pragma unroll 8
        for (int m = 0; m < 64; ++m) acc = fmaf(W_iouh[tid * 64 + m], s_hs[m], acc);
        s_iou[tid] = acc;
    }
    __syncthreads();
    if (tid < 64) {
        float iv = s_iou[tid], ov = s_iou[64 + tid], uv = s_iou[128 + tid];
        float cobj = fmaf(sigm(iv), tanh_f(uv), s_fc[tid]);
        float hobj = sigm(ov) * tanh_f(cobj);
        s_hobj[tid] = hobj;
        out[64 + tid] = cobj;
    }
    __syncthreads();
    if (tid < 64) {
        float acc = b_oout[tid];
#pragma unroll 8
        for (int m = 0; m < 64; ++m) acc = fmaf(W_oout[tid * 64 + m], s_hobj[m], acc);
        out[tid] = acc;
    }
}

// ---------------- launch ----------------
extern "C" void kernel_launch(void* const* d_in, const int* in_sizes, int n_in,
                              void* d_out, int out_size) {
    (void)in_sizes; (void)n_in; (void)out_size;
    const float* x      = (const float*)d_in[0];
    const float* W_num  = (const float*)d_in[1];
    const float* b_num  = (const float*)d_in[2];
    const float* W_ih   = (const float*)d_in[3];
    const float* W_hh   = (const float*)d_in[4];
    const float* b_ih   = (const float*)d_in[5];
    const float* b_hh   = (const float*)d_in[6];
    const float* W_aout = (const float*)d_in[7];
    const float* b_aout = (const float*)d_in[8];
    const float* W_fh   = (const float*)d_in[9];
    const float* b_fh   = (const float*)d_in[10];
    const float* W_iouh = (const float*)d_in[11];
    const float* b_iouh = (const float*)d_in[12];
    const float* W_oout = (const float*)d_in[13];
    const float* b_oout = (const float*)d_in[14];
    float* out = (float*)d_out;

    cudaFuncSetAttribute(lstm_kernel, cudaFuncAttributeMaxDynamicSharedMemorySize, SMEM_BYTES);

    precompute_kernel<<<1, 256>>>(W_ih, W_num, b_num, b_ih, b_hh);
    lstm_kernel<<<256, 256, SMEM_BYTES>>>(x, W_hh, W_aout, b_aout, W_fh, b_fh);
    final_kernel<<<1, 192>>>(out, W_iouh, b_iouh, W_oout, b_oout);
}

// round 3
// speedup vs baseline: 1.1123x; 1.1123x over previous
#include <cuda_runtime.h>

typedef unsigned long long ull;

// ---------------- device scratch ----------------
__device__ float g_FC[128 * 64];    // per-block partial sum of sigmoid(f)*c
__device__ float g_HS[128 * 64];    // per-block partial sum of h_hat

// ---------------- helpers ----------------
__device__ __forceinline__ ull fma2(ull a, ull b, ull c) {
    ull d;
    asm("fma.rn.f32x2 %0, %1, %2, %3;" : "=l"(d) : "l"(a), "l"(b), "l"(c));
    return d;
}
__device__ __forceinline__ float hadd2(ull v) {
    float lo, hi;
    asm("mov.b64 {%0, %1}, %2;" : "=f"(lo), "=f"(hi) : "l"(v));
    return lo + hi;
}
__device__ __forceinline__ float sigm(float x) {
    return __fdividef(1.0f, 1.0f + __expf(-x));
}
__device__ __forceinline__ float tanh_f(float x) {
    return __fdividef(2.0f, 1.0f + __expf(-2.0f * x)) - 1.0f;
}

// ---------------- kernel 1: batched LSTM scan + fused epilogue ----------------
// grid = 128 blocks (64 rows each), block = 256 threads (8 warps), 1 block/SM.
// warp w owns hidden dims [8w, 8w+8); lane l owns rows l and l+32.
// SMEM (floats): sW 16384 | sX 8192 | sH 2x4352 | sA 256 | sC 256 = 33792 fl = 135168 B
#define SMEM_FLOATS 33792
#define SMEM_BYTES  (SMEM_FLOATS * 4)
#define HSTRIDE 68   // 68 mod 32 == 4 -> conflict-free float4/ulonglong2 access

__global__ __launch_bounds__(256, 1)
void lstm_kernel(const float* __restrict__ x,
                 const float* __restrict__ W_hh,
                 const float* __restrict__ W_num,
                 const float* __restrict__ b_num,
                 const float* __restrict__ W_ih,
                 const float* __restrict__ b_ih,
                 const float* __restrict__ b_hh,
                 const float* __restrict__ W_aout,
                 const float* __restrict__ b_aout,
                 const float* __restrict__ W_fh,
                 const float* __restrict__ b_fh) {
    extern __shared__ float smem[];
    float* sW = smem;            // [256][64] W_hh rows
    float* sX = smem + 16384;    // [128][64] x tile, transposed
    float* sH = smem + 24576;    // 2 x [64][HSTRIDE] double-buffered h
    float* sA = smem + 33280;    // folded input-proj slope  (epilogue: b_aout|b_fh)
    float* sC = smem + 33536;    // folded input-proj offset + biases

    const int tid  = threadIdx.x;
    const int lane = tid & 31;
    const int wid  = tid >> 5;
    const int d0   = wid * 8;
    const int r0   = blockIdx.x * 64;

    // ---- staging ----
    {
        const float4* src = reinterpret_cast<const float4*>(W_hh);
        float4* dst = reinterpret_cast<float4*>(sW);
        for (int i = tid; i < 4096; i += 256) dst[i] = src[i];
    }
    for (int i = tid; i < 8192; i += 256) {
        int rr = i >> 7, tt = i & 127;
        sX[tt * 64 + rr] = x[(size_t)(r0 + rr) * 128 + tt];
    }
    for (int i = tid; i < 4352; i += 256) sH[i] = 0.f;  // zero read-buffer for t=0
    {
        // fold input projection: A = W_ih[:,:64]@W_num ; C = W_ih[:,:64]@b_num + b_ih + b_hh
        float a = 0.f, cc = 0.f;
#pragma unroll 8
        for (int dd = 0; dd < 64; ++dd) {
            float w = W_ih[tid * 128 + dd];
            a  = fmaf(w, W_num[dd], a);
            cc = fmaf(w, b_num[dd], cc);
        }
        sA[tid] = a;
        sC[tid] = cc + b_ih[tid] + b_hh[tid];
    }
    __syncthreads();

    float c0[8], c1[8];
#pragma unroll
    for (int u = 0; u < 8; ++u) { c0[u] = 0.f; c1[u] = 0.f; }

    // ---- scan ----
    for (int t = 0; t < 128; ++t) {
        const float xv0 = sX[t * 64 + lane];
        const float xv1 = sX[t * 64 + 32 + lane];
        const float* hbuf = sH + (t & 1) * 4352;
        float* hout = sH + ((t & 1) ^ 1) * 4352;

        ull h0[32], h1[32];
        {
            const ulonglong2* p0 = reinterpret_cast<const ulonglong2*>(hbuf + lane * HSTRIDE);
            const ulonglong2* p1 = reinterpret_cast<const ulonglong2*>(hbuf + (lane + 32) * HSTRIDE);
#pragma unroll
            for (int i = 0; i < 16; ++i) { ulonglong2 v = p0[i]; h0[2*i] = v.x; h0[2*i+1] = v.y; }
#pragma unroll
            for (int i = 0; i < 16; ++i) { ulonglong2 v = p1[i]; h1[2*i] = v.x; h1[2*i+1] = v.y; }
        }

        float hn0[8], hn1[8];
#pragma unroll
        for (int u = 0; u < 8; ++u) {
            const int d = d0 + u;
            const ulonglong2* Wi = reinterpret_cast<const ulonglong2*>(sW + d * 64);
            const ulonglong2* Wf = reinterpret_cast<const ulonglong2*>(sW + (64 + d) * 64);
            const ulonglong2* Wg = reinterpret_cast<const ulonglong2*>(sW + (128 + d) * 64);
            const ulonglong2* Wo = reinterpret_cast<const ulonglong2*>(sW + (192 + d) * 64);
            ull ai0 = 0, af0 = 0, ag0 = 0, ao0 = 0;
            ull ai1 = 0, af1 = 0, ag1 = 0, ao1 = 0;
#pragma unroll
            for (int q = 0; q < 16; ++q) {
                ulonglong2 wi = Wi[q], wf = Wf[q], wg = Wg[q], wo = Wo[q];
                ull a0 = h0[2*q], b0 = h0[2*q+1];
                ull a1 = h1[2*q], b1 = h1[2*q+1];
                ai0 = fma2(wi.x, a0, ai0); ai0 = fma2(wi.y, b0, ai0);
                ai1 = fma2(wi.x, a1, ai1); ai1 = fma2(wi.y, b1, ai1);
                af0 = fma2(wf.x, a0, af0); af0 = fma2(wf.y, b0, af0);
                af1 = fma2(wf.x, a1, af1); af1 = fma2(wf.y, b1, af1);
                ag0 = fma2(wg.x, a0, ag0); ag0 = fma2(wg.y, b0, ag0);
                ag1 = fma2(wg.x, a1, ag1); ag1 = fma2(wg.y, b1, ag1);
                ao0 = fma2(wo.x, a0, ao0); ao0 = fma2(wo.y, b0, ao0);
                ao1 = fma2(wo.x, a1, ao1); ao1 = fma2(wo.y, b1, ao1);
            }
            const float A_i = sA[d],       C_i = sC[d];
            const float A_f = sA[64 + d],  C_f = sC[64 + d];
            const float A_g = sA[128 + d], C_g = sC[128 + d];
            const float A_o = sA[192 + d], C_o = sC[192 + d];
            {
                float gi = hadd2(ai0) + fmaf(xv0, A_i, C_i);
                float gf = hadd2(af0) + fmaf(xv0, A_f, C_f);
                float gg = hadd2(ag0) + fmaf(xv0, A_g, C_g);
                float go = hadd2(ao0) + fmaf(xv0, A_o, C_o);
                float I = sigm(gi), F = sigm(gf), G = tanh_f(gg), O = sigm(go);
                c0[u]  = fmaf(F, c0[u], I * G);
                hn0[u] = O * tanh_f(c0[u]);
            }
            {
                float gi = hadd2(ai1) + fmaf(xv1, A_i, C_i);
                float gf = hadd2(af1) + fmaf(xv1, A_f, C_f);
                float gg = hadd2(ag1) + fmaf(xv1, A_g, C_g);
                float go = hadd2(ao1) + fmaf(xv1, A_o, C_o);
                float I = sigm(gi), F = sigm(gf), G = tanh_f(gg), O = sigm(go);
                c1[u]  = fmaf(F, c1[u], I * G);
                hn1[u] = O * tanh_f(c1[u]);
            }
        }
        {
            float4* dst0 = reinterpret_cast<float4*>(hout + lane * HSTRIDE + d0);
            float4* dst1 = reinterpret_cast<float4*>(hout + (lane + 32) * HSTRIDE + d0);
            dst0[0] = make_float4(hn0[0], hn0[1], hn0[2], hn0[3]);
            dst0[1] = make_float4(hn0[4], hn0[5], hn0[6], hn0[7]);
            dst1[0] = make_float4(hn1[0], hn1[1], hn1[2], hn1[3]);
            dst1[1] = make_float4(hn1[4], hn1[5], hn1[6], hn1[7]);
        }
        __syncthreads();
    }

    // ---- epilogue: h_hat = h@W_aout.T + b_aout ; f = h_hat@W_fh.T + b_fh ----
    // final h is in buffer 0 (step 127 wrote ((127&1)^1)=0)
    for (int i = tid; i < 4096; i += 256) {
        sW[i]        = W_aout[i];
        sW[4096 + i] = W_fh[i];
    }
    if (tid < 64) { sA[tid] = b_aout[tid]; sA[64 + tid] = b_fh[tid]; }
    __syncthreads();

    ull h0[32], h1[32];
    {
        const ulonglong2* p0 = reinterpret_cast<const ulonglong2*>(sH + lane * HSTRIDE);
        const ulonglong2* p1 = reinterpret_cast<const ulonglong2*>(sH + (lane + 32) * HSTRIDE);
#pragma unroll
        for (int i = 0; i < 16; ++i) { ulonglong2 v = p0[i]; h0[2*i] = v.x; h0[2*i+1] = v.y; }
#pragma unroll
        for (int i = 0; i < 16; ++i) { ulonglong2 v = p1[i]; h1[2*i] = v.x; h1[2*i+1] = v.y; }
    }
    float hh0[8], hh1[8];
#pragma unroll
    for (int u = 0; u < 8; ++u) {
        const int d = d0 + u;
        const ulonglong2* Wa = reinterpret_cast<const ulonglong2*>(sW + d * 64);
        ull a0 = 0, a1 = 0;
#pragma unroll
        for (int q = 0; q < 16; ++q) {
            ulonglong2 w = Wa[q];
            a0 = fma2(w.x, h0[2*q], a0); a0 = fma2(w.y, h0[2*q+1], a0);
            a1 = fma2(w.x, h1[2*q], a1); a1 = fma2(w.y, h1[2*q+1], a1);
        }
        hh0[u] = hadd2(a0) + sA[d];
        hh1[u] = hadd2(a1) + sA[d];
    }
    __syncthreads();
    // publish h_hat rows into sX area (stride HSTRIDE)
    {
        float4* q0 = reinterpret_cast<float4*>(sX + lane * HSTRIDE + d0);
        float4* q1 = reinterpret_cast<float4*>(sX + (lane + 32) * HSTRIDE + d0);
        q0[0] = make_float4(hh0[0], hh0[1], hh0[2], hh0[3]);
        q0[1] = make_float4(hh0[4], hh0[5], hh0[6], hh0[7]);
        q1[0] = make_float4(hh1[0], hh1[1], hh1[2], hh1[3]);
        q1[1] = make_float4(hh1[4], hh1[5], hh1[6], hh1[7]);
    }
    __syncthreads();
    ull q0r[32], q1r[32];
    {
        const ulonglong2* p0 = reinterpret_cast<const ulonglong2*>(sX + lane * HSTRIDE);
        const ulonglong2* p1 = reinterpret_cast<const ulonglong2*>(sX + (lane + 32) * HSTRIDE);
#pragma unroll
        for (int i = 0; i < 16; ++i) { ulonglong2 v = p0[i]; q0r[2*i] = v.x; q0r[2*i+1] = v.y; }
#pragma unroll
        for (int i = 0; i < 16; ++i) { ulonglong2 v = p1[i]; q1r[2*i] = v.x; q1r[2*i+1] = v.y; }
    }
#pragma unroll
    for (int u = 0; u < 8; ++u) {
        const int d = d0 + u;
        const ulonglong2* Wf2 = reinterpret_cast<const ulonglong2*>(sW + 4096 + d * 64);
        ull a0 = 0, a1 = 0;
#pragma unroll
        for (int q = 0; q < 16; ++q) {
            ulonglong2 w = Wf2[q];
            a0 = fma2(w.x, q0r[2*q], a0); a0 = fma2(w.y, q0r[2*q+1], a0);
            a1 = fma2(w.x, q1r[2*q], a1); a1 = fma2(w.y, q1r[2*q+1], a1);
        }
        float fv0 = hadd2(a0) + sA[64 + d];
        float fv1 = hadd2(a1) + sA[64 + d];
        float fc = sigm(fv0) * c0[u] + sigm(fv1) * c1[u];
        float hs = hh0[u] + hh1[u];
#pragma unroll
        for (int off = 16; off; off >>= 1) {
            fc += __shfl_down_sync(0xffffffffu, fc, off);
            hs += __shfl_down_sync(0xffffffffu, hs, off);
        }
        if (lane == 0) {
            g_FC[blockIdx.x * 64 + d] = fc;
            g_HS[blockIdx.x * 64 + d] = hs;
        }
    }
}

// ---------------- kernel 2: deterministic final reduction + objective cell ----------------
__global__ void final_kernel(float* __restrict__ out,
                             const float* __restrict__ W_iouh,
                             const float* __restrict__ b_iouh,
                             const float* __restrict__ W_oout,
                             const float* __restrict__ b_oout) {
    __shared__ float s_fc[64], s_hs[64], s_iou[192], s_hobj[64];
    int tid = threadIdx.x;
    if (tid < 64) {
        float fc = 0.f, hs = 0.f;
#pragma unroll 8
        for (int b = 0; b < 128; ++b) {
            fc += g_FC[b * 64 + tid];
            hs += g_HS[b * 64 + tid];
        }
        s_fc[tid] = fc;
        s_hs[tid] = hs;
    }
    __syncthreads();
    if (tid < 192) {
        float acc = b_iouh[tid];
#pragma unroll 8
        for (int m = 0; m < 64; ++m) acc = fmaf(W_iouh[tid * 64 + m], s_hs[m], acc);
        s_iou[tid] = acc;
    }
    __syncthreads();
    if (tid < 64) {
        float iv = s_iou[tid], ov = s_iou[64 + tid], uv = s_iou[128 + tid];
        float cobj = fmaf(sigm(iv), tanh_f(uv), s_fc[tid]);
        float hobj = sigm(ov) * tanh_f(cobj);
        s_hobj[tid] = hobj;
        out[64 + tid] = cobj;
    }
    __syncthreads();
    if (tid < 64) {
        float acc = b_oout[tid];
#pragma unroll 8
        for (int m = 0; m < 64; ++m) acc = fmaf(W_oout[tid * 64 + m], s_hobj[m], acc);
        out[tid] = acc;
    }
}

// ---------------- launch ----------------
extern "C" void kernel_launch(void* const* d_in, const int* in_sizes, int n_in,
                              void* d_out, int out_size) {
    (void)in_sizes; (void)n_in; (void)out_size;
    const float* x      = (const float*)d_in[0];
    const float* W_num  = (const float*)d_in[1];
    const float* b_num  = (const float*)d_in[2];
    const float* W_ih   = (const float*)d_in[3];
    const float* W_hh   = (const float*)d_in[4];
    const float* b_ih   = (const float*)d_in[5];
    const float* b_hh   = (const float*)d_in[6];
    const float* W_aout = (const float*)d_in[7];
    const float* b_aout = (const float*)d_in[8];
    const float* W_fh   = (const float*)d_in[9];
    const float* b_fh   = (const float*)d_in[10];
    const float* W_iouh = (const float*)d_in[11];
    const float* b_iouh = (const float*)d_in[12];
    const float* W_oout = (const float*)d_in[13];
    const float* b_oout = (const float*)d_in[14];
    float* out = (float*)d_out;

    cudaFuncSetAttribute(lstm_kernel, cudaFuncAttributeMaxDynamicSharedMemorySize, SMEM_BYTES);

    lstm_kernel<<<128, 256, SMEM_BYTES>>>(x, W_hh, W_num, b_num, W_ih, b_ih, b_hh,
                                          W_aout, b_aout, W_fh, b_fh);
    final_kernel<<<1, 192>>>(out, W_iouh, b_iouh, W_oout, b_oout);
}